// round 10
// baseline (speedup 1.0000x reference)
#include <cuda_runtime.h>
#include <math.h>

#define B_   32
#define T_   2048
#define D_   1024
#define MEM_ 64
#define HID_ 512   // D/2
#define NC_  13    // time chunks per batch in mean phase
#define NT0_ (B_ * NC_)   // 416 phase-0 tiles
#define NB_  444   // 3 blocks/SM x 148 SMs; co-residency via __launch_bounds__(256,3)

// ---------------- device scratch (no allocations allowed) ----------------
__device__ __align__(16) float g_part[B_ * NC_ * D_];  // mean partials [b][c][d]
__device__ __align__(16) float g_pxp [8 * B_ * D_];    // xp partials   [ks][b][e]
__device__ __align__(16) float g_ph  [16 * B_ * HID_]; // h partials    [ks][b][j]
__device__ __align__(16) float g_psim[16 * B_ * MEM_]; // sims partials [ks][b][m]
__device__ __align__(16) float g_pksq[16 * MEM_];      // |key|^2 partials
__device__ float g_pxsq[16 * B_];
__device__ float g_pd0 [16 * B_];
__device__ float g_pd1 [16 * B_];
__device__ float g_pn0 [16];
__device__ float g_pn1 [16];
__device__ unsigned long long g_bar;   // monotonic grid-barrier counter (never reset -> replay safe)

// ---------------- dynamic smem pool layout ----------------
#define SA1_STRIDE 129
#define SW1_OFF    (32 * SA1_STRIDE)              // 4128 floats
#define SW1_STRIDE 132
#define POOL_FLOATS (SW1_OFF + 64 * SW1_STRIDE)   // 12576 floats
#define SMEM_BYTES  (POOL_FLOATS * 4)             // 50304 B
#define SA2_STRIDE 65
#define SW2_OFF    (32 * SA2_STRIDE)              // 2080
#define SW2_STRIDE 68
#define MK0_OFF    (SW2_OFF + 64 * SW2_STRIDE)    // 6432
#define MK1_OFF    (MK0_OFF + 64)                 // 6496

// ---------------- grid barrier: monotonic counter, all NB_ blocks resident ----------------
__device__ __forceinline__ void gridBarrier() {
    __threadfence();
    __syncthreads();
    if (threadIdx.x == 0) {
        unsigned long long a = atomicAdd(&g_bar, 1ULL);
        unsigned long long target = (a / NB_ + 1ULL) * (unsigned long long)NB_;
        volatile unsigned long long* p = &g_bar;
        while (*p < target) { }
        __threadfence();
    }
    __syncthreads();
}

__global__ __launch_bounds__(256, 3) void k_all(
    const float* __restrict__ x,
    const float* __restrict__ mkey0, const float* __restrict__ mkey1,
    const float* __restrict__ keym,  const float* __restrict__ valm,
    const float* __restrict__ W1,    const float* __restrict__ mlp_b1,
    const float* __restrict__ w2,    const float* __restrict__ b2,
    const float* __restrict__ cw,    const float* __restrict__ cb,
    const float* __restrict__ Wxa,   const float* __restrict__ xa_b,
    const float* __restrict__ thr,   float* __restrict__ out) {
    extern __shared__ __align__(16) float pool[];
    int bid = blockIdx.x;
    int tid = threadIdx.x;

    // ===== P1 weight preload (blocks 0..127): latency hides under phase 0 =====
    if (bid < 128) {
        int et = bid >> 3;
        int e = tid >> 2, q = tid & 3;
        const float4* src = (const float4*)(Wxa + (size_t)(et * 64 + e) * D_ + (bid & 7) * 128) + q;
        #pragma unroll
        for (int i = 0; i < 8; i++) {
            float4 t = src[i * 4];
            *(float4*)&pool[SW1_OFF + e * SW1_STRIDE + (q + i * 4) * 4] = t;
        }
    }

    // ===== Phase 0: mean over T, partial sums (416 tiles: [batch][chunk]) =====
    if (bid < NT0_) {
        int b = bid / NC_;
        int c = bid - b * NC_;
        int t0 = (c * T_) / NC_;
        int t1 = ((c + 1) * T_) / NC_;
        const float4* p = (const float4*)(x + (size_t)b * T_ * D_) + tid;
        float4 a0 = {0,0,0,0}, a1 = a0, a2 = a0, a3 = a0;
        int t = t0;
        for (; t + 8 <= t1; t += 8) {
            float4 v0 = __ldcs(&p[(t + 0) * (D_/4)]);
            float4 v1 = __ldcs(&p[(t + 1) * (D_/4)]);
            float4 v2 = __ldcs(&p[(t + 2) * (D_/4)]);
            float4 v3 = __ldcs(&p[(t + 3) * (D_/4)]);
            float4 v4 = __ldcs(&p[(t + 4) * (D_/4)]);
            float4 v5 = __ldcs(&p[(t + 5) * (D_/4)]);
            float4 v6 = __ldcs(&p[(t + 6) * (D_/4)]);
            float4 v7 = __ldcs(&p[(t + 7) * (D_/4)]);
            a0.x += v0.x + v4.x; a0.y += v0.y + v4.y; a0.z += v0.z + v4.z; a0.w += v0.w + v4.w;
            a1.x += v1.x + v5.x; a1.y += v1.y + v5.y; a1.z += v1.z + v5.z; a1.w += v1.w + v5.w;
            a2.x += v2.x + v6.x; a2.y += v2.y + v6.y; a2.z += v2.z + v6.z; a2.w += v2.w + v6.w;
            a3.x += v3.x + v7.x; a3.y += v3.y + v7.y; a3.z += v3.z + v7.z; a3.w += v3.w + v7.w;
        }
        for (; t < t1; t++) {
            float4 v = __ldcs(&p[t * (D_/4)]);
            a0.x += v.x; a0.y += v.y; a0.z += v.z; a0.w += v.w;
        }
        float4 s;
        s.x = (a0.x + a1.x) + (a2.x + a3.x);
        s.y = (a0.y + a1.y) + (a2.y + a3.y);
        s.z = (a0.z + a1.z) + (a2.z + a3.z);
        s.w = (a0.w + a1.w) + (a2.w + a3.w);
        ((float4*)g_part)[(b * NC_ + c) * (D_/4) + tid] = s;
    }

    gridBarrier();

    // ===== Phase 1: xp split-K GEMM (128 tiles; weights already in smem) =====
    if (bid < 128) {
        int et = bid >> 3, ks = bid & 7;
        int e0 = et * 64, k0 = ks * 128;
        {   // A 32x128: reduce NC_ time-chunk partials * 1/T
            int bb  = tid >> 3;
            int kk0 = (tid & 7) * 16;
            float4 acc[4] = {{0,0,0,0},{0,0,0,0},{0,0,0,0},{0,0,0,0}};
            #pragma unroll
            for (int c = 0; c < NC_; c++) {
                const float4* src = (const float4*)(g_part + ((size_t)bb * NC_ + c) * D_ + k0 + kk0);
                #pragma unroll
                for (int j = 0; j < 4; j++) {
                    float4 v = src[j];
                    acc[j].x += v.x; acc[j].y += v.y; acc[j].z += v.z; acc[j].w += v.w;
                }
            }
            const float invT = 1.0f / (float)T_;
            #pragma unroll
            for (int j = 0; j < 4; j++) {
                pool[bb * SA1_STRIDE + kk0 + 4*j + 0] = acc[j].x * invT;
                pool[bb * SA1_STRIDE + kk0 + 4*j + 1] = acc[j].y * invT;
                pool[bb * SA1_STRIDE + kk0 + 4*j + 2] = acc[j].z * invT;
                pool[bb * SA1_STRIDE + kk0 + 4*j + 3] = acc[j].w * invT;
            }
        }
        __syncthreads();
        int tb = tid & 15, te = tid >> 4;
        float accA[4] = {0,0,0,0}, accB[4] = {0,0,0,0};
        #pragma unroll 4
        for (int k = 0; k < 128; k++) {
            float a0 = pool[tb * SA1_STRIDE + k];
            float a1 = pool[(tb + 16) * SA1_STRIDE + k];
            #pragma unroll
            for (int i = 0; i < 4; i++) {
                float w = pool[SW1_OFF + (te * 4 + i) * SW1_STRIDE + k];
                accA[i] += a0 * w;
                accB[i] += a1 * w;
            }
        }
        #pragma unroll
        for (int i = 0; i < 4; i++) {
            g_pxp[((size_t)ks * B_ + tb     ) * D_ + e0 + te * 4 + i] = accA[i];
            g_pxp[((size_t)ks * B_ + tb + 16) * D_ + e0 + te * 4 + i] = accB[i];
        }
    }

    gridBarrier();

    // ===== Phase 2: MLP GEMM + attention-logits GEMM (144 tiles) =====
    if (bid < 144) {
        int et = bid >> 4, ks = bid & 15;   // et 0..8, ks 0..15
        int k0 = ks * 64;
        bool attn = (et == 8);
        {   // weight tile 64x64 coalesced
            int e = tid >> 2, q = tid & 3;
            const float* base = attn ? (keym + (size_t)e * D_ + k0)
                                     : (W1 + (size_t)(et * 64 + e) * D_ + k0);
            const float4* src = (const float4*)base + q;
            #pragma unroll
            for (int i = 0; i < 4; i++) {
                float4 t = src[i * 4];
                *(float4*)&pool[SW2_OFF + e * SW2_STRIDE + (q + i * 4) * 4] = t;
            }
        }
        if (attn && tid >= 192) {
            int i = tid - 192;
            pool[MK0_OFF + i] = mkey0[k0 + i];
            pool[MK1_OFF + i] = mkey1[k0 + i];
        }
        {   // A 32x64: reduce 8 xp partials + bias (identical order everywhere)
            int bb  = tid >> 3;
            int kk0 = (tid & 7) * 8;
            float4 acc[2] = {{0,0,0,0},{0,0,0,0}};
            #pragma unroll
            for (int s = 0; s < 8; s++) {
                const float4* src = (const float4*)(g_pxp + ((size_t)s * B_ + bb) * D_ + k0 + kk0);
                #pragma unroll
                for (int j = 0; j < 2; j++) {
                    float4 v = src[j];
                    acc[j].x += v.x; acc[j].y += v.y; acc[j].z += v.z; acc[j].w += v.w;
                }
            }
            const float4* bv = (const float4*)(xa_b + k0 + kk0);
            #pragma unroll
            for (int j = 0; j < 2; j++) {
                float4 bb4 = bv[j];
                pool[bb * SA2_STRIDE + kk0 + 4*j + 0] = acc[j].x + bb4.x;
                pool[bb * SA2_STRIDE + kk0 + 4*j + 1] = acc[j].y + bb4.y;
                pool[bb * SA2_STRIDE + kk0 + 4*j + 2] = acc[j].z + bb4.z;
                pool[bb * SA2_STRIDE + kk0 + 4*j + 3] = acc[j].w + bb4.w;
            }
        }
        __syncthreads();
        int tb = tid & 15, te = tid >> 4;
        float accA[4] = {0,0,0,0}, accB[4] = {0,0,0,0};
        #pragma unroll 4
        for (int k = 0; k < 64; k++) {
            float a0 = pool[tb * SA2_STRIDE + k];
            float a1 = pool[(tb + 16) * SA2_STRIDE + k];
            #pragma unroll
            for (int i = 0; i < 4; i++) {
                float w = pool[SW2_OFF + (te * 4 + i) * SW2_STRIDE + k];
                accA[i] += a0 * w;
                accB[i] += a1 * w;
            }
        }
        if (!attn) {
            int e0 = et * 64;
            #pragma unroll
            for (int i = 0; i < 4; i++) {
                g_ph[((size_t)ks * B_ + tb     ) * HID_ + e0 + te * 4 + i] = accA[i];
                g_ph[((size_t)ks * B_ + tb + 16) * HID_ + e0 + te * 4 + i] = accB[i];
            }
        } else {
            #pragma unroll
            for (int i = 0; i < 4; i++) {
                g_psim[((size_t)ks * B_ + tb     ) * MEM_ + te * 4 + i] = accA[i];
                g_psim[((size_t)ks * B_ + tb + 16) * MEM_ + te * 4 + i] = accB[i];
            }
            if (tid < 64) {
                float s = 0.f;
                #pragma unroll 8
                for (int k = 0; k < 64; k++) { float w = pool[SW2_OFF + tid * SW2_STRIDE + k]; s += w * w; }
                g_pksq[ks * MEM_ + tid] = s;
            } else if (tid < 96) {
                int bb = tid - 64;
                float sx = 0.f, s0 = 0.f, s1 = 0.f;
                #pragma unroll 8
                for (int k = 0; k < 64; k++) {
                    float a = pool[bb * SA2_STRIDE + k];
                    sx += a * a;
                    s0 += a * pool[MK0_OFF + k];
                    s1 += a * pool[MK1_OFF + k];
                }
                g_pxsq[ks * B_ + bb] = sx;
                g_pd0 [ks * B_ + bb] = s0;
                g_pd1 [ks * B_ + bb] = s1;
            } else if (tid == 96) {
                float s = 0.f;
                #pragma unroll 8
                for (int k = 0; k < 64; k++) s += pool[MK0_OFF + k] * pool[MK0_OFF + k];
                g_pn0[ks] = s;
            } else if (tid == 97) {
                float s = 0.f;
                #pragma unroll 8
                for (int k = 0; k < 64; k++) s += pool[MK1_OFF + k] * pool[MK1_OFF + k];
                g_pn1[ks] = s;
            }
        }
    }

    gridBarrier();

    // ===== Phase 3: tail (32 tiles, one per batch) =====
    if (bid < B_) {
        int b = bid;
        int lane = tid & 31;
        int w = tid >> 5;
        float* logits = pool;        // [64]
        float* sc     = pool + 64;   // [8]
        float* rbuf   = pool + 72;   // [8]

        float2 th[16];
        #pragma unroll
        for (int s = 0; s < 16; s++)
            th[s] = ((const float2*)(g_ph + ((size_t)s * B_ + b) * HID_))[tid];

        float simsum = 0.f, ksum = 0.f;
        if (tid < MEM_) {
            #pragma unroll
            for (int s = 0; s < 16; s++) simsum += g_psim[((size_t)s * B_ + b) * MEM_ + tid];
            #pragma unroll
            for (int s = 0; s < 16; s++) ksum += g_pksq[s * MEM_ + tid];
        } else if (tid >= 64 && tid < 72) {
            int j = tid - 64;
            float s = 0.f;
            if (j < 3) {
                const float* src = (j == 0) ? g_pxsq : (j == 1) ? g_pd0 : g_pd1;
                #pragma unroll
                for (int k = 0; k < 16; k++) s += src[k * B_ + b];
            } else if (j < 6) {
                if (b > 0) {
                    const float* src = (j == 3) ? g_pxsq : (j == 4) ? g_pd0 : g_pd1;
                    #pragma unroll
                    for (int k = 0; k < 16; k++) s += src[k * B_ + (b - 1)];
                }
            } else {
                const float* src = (j == 6) ? g_pn0 : g_pn1;
                #pragma unroll
                for (int k = 0; k < 16; k++) s += src[k];
            }
            sc[j] = s;
        }
        __syncthreads();

        float nx = sqrtf(sc[0]);
        if (tid < MEM_) {
            float nk = sqrtf(ksum);
            logits[tid] = simsum / fmaxf(nx, 1e-12f) / fmaxf(nk, 1e-12f) * (1.0f / 32.0f);
        }

        float2 b1v = ((const float2*)mlp_b1)[tid];
        float2 w2v = ((const float2*)w2)[tid];
        float2 hv = {0.f, 0.f};
        #pragma unroll
        for (int s = 0; s < 16; s++) { hv.x += th[s].x; hv.y += th[s].y; }
        hv.x += b1v.x; hv.y += b1v.y;
        float h0 = hv.x / (1.0f + expf(-hv.x));
        float h1 = hv.y / (1.0f + expf(-hv.y));
        float mp = h0 * w2v.x + h1 * w2v.y;
        #pragma unroll
        for (int o = 16; o > 0; o >>= 1) mp += __shfl_down_sync(0xffffffffu, mp, o);
        __syncthreads();                    // orders logits[] before softmax read
        if (lane == 0) rbuf[w] = mp;
        __syncthreads();
        float mlp_out = rbuf[0];
        #pragma unroll
        for (int i = 1; i < 8; i++) mlp_out += rbuf[i];
        mlp_out += b2[0];

        float sn0 = sqrtf(sc[6]), sn1 = sqrtf(sc[7]);
        float s0 = sc[1] / fmaxf(nx * sn0, 1e-8f);
        float s1 = sc[2] / fmaxf(nx * sn1, 1e-8f);
        int best = (s1 > s0) ? 1 : 0;
        float changed = 1.0f;
        if (b > 0) {
            float pn  = sqrtf(sc[3]);
            float ps0 = sc[4] / fmaxf(pn * sn0, 1e-8f);
            float ps1 = sc[5] / fmaxf(pn * sn1, 1e-8f);
            int pbest = (ps1 > ps0) ? 1 : 0;
            changed = (best != pbest) ? 1.0f : 0.0f;
        }

        if (tid < 32) {
            float l0 = logits[tid], l1 = logits[tid + 32];
            float mx = fmaxf(l0, l1);
            #pragma unroll
            for (int o = 16; o > 0; o >>= 1) mx = fmaxf(mx, __shfl_xor_sync(0xffffffffu, mx, o));
            float e0 = expf(l0 - mx), e1 = expf(l1 - mx);
            float ssum = e0 + e1;
            float vsum = e0 * valm[tid] + e1 * valm[tid + 32];
            #pragma unroll
            for (int o = 16; o > 0; o >>= 1) {
                ssum += __shfl_down_sync(0xffffffffu, ssum, o);
                vsum += __shfl_down_sync(0xffffffffu, vsum, o);
            }
            if (tid == 0) {
                float mem_val = vsum / ssum;
                out[b]      = (changed > thr[0]) ? 1.0f : 0.0f;
                out[B_ + b] = cw[0] * mem_val + cw[1] * mlp_out + cb[0];
            }
        }
    }
}

// ---------------- launch ----------------
extern "C" void kernel_launch(void* const* d_in, const int* in_sizes, int n_in,
                              void* d_out, int out_size) {
    const float* x       = (const float*)d_in[0];
    const float* mkey0   = (const float*)d_in[1];
    const float* mkey1   = (const float*)d_in[2];
    const float* keym    = (const float*)d_in[3];
    const float* valm    = (const float*)d_in[4];
    const float* mlp_w1  = (const float*)d_in[5];
    const float* mlp_b1  = (const float*)d_in[6];
    const float* mlp_w2  = (const float*)d_in[7];
    const float* mlp_b2  = (const float*)d_in[8];
    const float* cw      = (const float*)d_in[9];
    const float* cb      = (const float*)d_in[10];
    const float* xa_w    = (const float*)d_in[11];
    const float* xa_b    = (const float*)d_in[12];
    const float* thr     = (const float*)d_in[13];
    float* out = (float*)d_out;

    cudaFuncSetAttribute(k_all, cudaFuncAttributeMaxDynamicSharedMemorySize, SMEM_BYTES);
    k_all<<<NB_, 256, SMEM_BYTES>>>(x, mkey0, mkey1, keym, valm,
                                    mlp_w1, mlp_b1, mlp_w2, mlp_b2,
                                    cw, cb, xa_w, xa_b, thr, out);
}

// round 11
// speedup vs baseline: 1.1231x; 1.1231x over previous
#include <cuda_runtime.h>
#include <math.h>

#define B_   32
#define T_   2048
#define D_   1024
#define MEM_ 64
#define HID_ 512   // D/2
#define NC_  9     // time chunks per batch in mean phase
#define NT0_ (B_ * NC_)   // 288 phase-0 tiles
#define NB_  296   // 2 blocks/SM x 148 SMs; co-residency via __launch_bounds__(256,2)

// ---------------- device scratch (no allocations allowed) ----------------
__device__ __align__(16) float g_part[B_ * NC_ * D_];  // mean partials [b][c][d]
__device__ __align__(16) float g_pxp [8 * B_ * D_];    // xp partials   [ks][b][e]
__device__ __align__(16) float g_ph  [16 * B_ * HID_]; // h partials    [ks][b][j]
__device__ __align__(16) float g_psim[16 * B_ * MEM_]; // sims partials [ks][b][m]
__device__ __align__(16) float g_pksq[16 * MEM_];      // |key|^2 partials
__device__ float g_pxsq[16 * B_];
__device__ float g_pd0 [16 * B_];
__device__ float g_pd1 [16 * B_];
__device__ float g_pn0 [16];
__device__ float g_pn1 [16];
__device__ unsigned long long g_bar;   // monotonic grid-barrier counter (never reset -> replay safe)

// ---------------- dynamic smem pool layout ----------------
#define SA1_STRIDE 129
#define SW1_OFF    (32 * SA1_STRIDE)              // 4128 floats
#define SW1_STRIDE 132
#define POOL_FLOATS (SW1_OFF + 64 * SW1_STRIDE)   // 12576 floats
#define SMEM_BYTES  (POOL_FLOATS * 4)             // 50304 B
#define SA2_STRIDE 65
#define SW2_OFF    (32 * SA2_STRIDE)              // 2080
#define SW2_STRIDE 68
#define MK0_OFF    (SW2_OFF + 64 * SW2_STRIDE)    // 6432
#define MK1_OFF    (MK0_OFF + 64)                 // 6496

// ---------------- grid barrier: monotonic counter, all NB_ blocks resident ----------------
__device__ __forceinline__ void gridBarrier() {
    __threadfence();
    __syncthreads();
    if (threadIdx.x == 0) {
        unsigned long long a = atomicAdd(&g_bar, 1ULL);
        unsigned long long target = (a / NB_ + 1ULL) * (unsigned long long)NB_;
        volatile unsigned long long* p = &g_bar;
        while (*p < target) { }
        __threadfence();
    }
    __syncthreads();
}

__global__ __launch_bounds__(256, 2) void k_all(
    const float* __restrict__ x,
    const float* __restrict__ mkey0, const float* __restrict__ mkey1,
    const float* __restrict__ keym,  const float* __restrict__ valm,
    const float* __restrict__ W1,    const float* __restrict__ mlp_b1,
    const float* __restrict__ w2,    const float* __restrict__ b2,
    const float* __restrict__ cw,    const float* __restrict__ cb,
    const float* __restrict__ Wxa,   const float* __restrict__ xa_b,
    const float* __restrict__ thr,   float* __restrict__ out) {
    extern __shared__ __align__(16) float pool[];
    int bid = blockIdx.x;
    int tid = threadIdx.x;

    // ===== P1 weight preload (blocks 0..127): latency hides under phase 0 =====
    if (bid < 128) {
        int et = bid >> 3;
        int e = tid >> 2, q = tid & 3;
        const float4* src = (const float4*)(Wxa + (size_t)(et * 64 + e) * D_ + (bid & 7) * 128) + q;
        #pragma unroll
        for (int i = 0; i < 8; i++) {
            float4 t = src[i * 4];
            *(float4*)&pool[SW1_OFF + e * SW1_STRIDE + (q + i * 4) * 4] = t;
        }
    }

    // ===== Phase 0: mean over T, partial sums (288 tiles: [batch][chunk]) =====
    if (bid < NT0_) {
        int b = bid / NC_;
        int c = bid - b * NC_;
        int t0 = (c * T_) / NC_;
        int t1 = ((c + 1) * T_) / NC_;
        const float4* p = (const float4*)(x + (size_t)b * T_ * D_) + tid;
        float4 a0 = {0,0,0,0}, a1 = a0, a2 = a0, a3 = a0, a4 = a0, a5 = a0, a6 = a0, a7 = a0;
        int t = t0;
        for (; t + 8 <= t1; t += 8) {
            float4 v0 = __ldcs(&p[(t + 0) * (D_/4)]);
            float4 v1 = __ldcs(&p[(t + 1) * (D_/4)]);
            float4 v2 = __ldcs(&p[(t + 2) * (D_/4)]);
            float4 v3 = __ldcs(&p[(t + 3) * (D_/4)]);
            float4 v4 = __ldcs(&p[(t + 4) * (D_/4)]);
            float4 v5 = __ldcs(&p[(t + 5) * (D_/4)]);
            float4 v6 = __ldcs(&p[(t + 6) * (D_/4)]);
            float4 v7 = __ldcs(&p[(t + 7) * (D_/4)]);
            a0.x += v0.x; a0.y += v0.y; a0.z += v0.z; a0.w += v0.w;
            a1.x += v1.x; a1.y += v1.y; a1.z += v1.z; a1.w += v1.w;
            a2.x += v2.x; a2.y += v2.y; a2.z += v2.z; a2.w += v2.w;
            a3.x += v3.x; a3.y += v3.y; a3.z += v3.z; a3.w += v3.w;
            a4.x += v4.x; a4.y += v4.y; a4.z += v4.z; a4.w += v4.w;
            a5.x += v5.x; a5.y += v5.y; a5.z += v5.z; a5.w += v5.w;
            a6.x += v6.x; a6.y += v6.y; a6.z += v6.z; a6.w += v6.w;
            a7.x += v7.x; a7.y += v7.y; a7.z += v7.z; a7.w += v7.w;
        }
        for (; t < t1; t++) {
            float4 v = __ldcs(&p[t * (D_/4)]);
            a0.x += v.x; a0.y += v.y; a0.z += v.z; a0.w += v.w;
        }
        float4 s;
        s.x = ((a0.x + a1.x) + (a2.x + a3.x)) + ((a4.x + a5.x) + (a6.x + a7.x));
        s.y = ((a0.y + a1.y) + (a2.y + a3.y)) + ((a4.y + a5.y) + (a6.y + a7.y));
        s.z = ((a0.z + a1.z) + (a2.z + a3.z)) + ((a4.z + a5.z) + (a6.z + a7.z));
        s.w = ((a0.w + a1.w) + (a2.w + a3.w)) + ((a4.w + a5.w) + (a6.w + a7.w));
        ((float4*)g_part)[(b * NC_ + c) * (D_/4) + tid] = s;
    }

    gridBarrier();

    // ===== Phase 1: xp split-K GEMM (128 tiles; weights already in smem) =====
    if (bid < 128) {
        int et = bid >> 3, ks = bid & 7;
        int e0 = et * 64, k0 = ks * 128;
        {   // A 32x128: reduce NC_ time-chunk partials * 1/T
            int bb  = tid >> 3;
            int kk0 = (tid & 7) * 16;
            float4 acc[4] = {{0,0,0,0},{0,0,0,0},{0,0,0,0},{0,0,0,0}};
            #pragma unroll
            for (int c = 0; c < NC_; c++) {
                const float4* src = (const float4*)(g_part + ((size_t)bb * NC_ + c) * D_ + k0 + kk0);
                #pragma unroll
                for (int j = 0; j < 4; j++) {
                    float4 v = src[j];
                    acc[j].x += v.x; acc[j].y += v.y; acc[j].z += v.z; acc[j].w += v.w;
                }
            }
            const float invT = 1.0f / (float)T_;
            #pragma unroll
            for (int j = 0; j < 4; j++) {
                pool[bb * SA1_STRIDE + kk0 + 4*j + 0] = acc[j].x * invT;
                pool[bb * SA1_STRIDE + kk0 + 4*j + 1] = acc[j].y * invT;
                pool[bb * SA1_STRIDE + kk0 + 4*j + 2] = acc[j].z * invT;
                pool[bb * SA1_STRIDE + kk0 + 4*j + 3] = acc[j].w * invT;
            }
        }
        __syncthreads();
        int tb = tid & 15, te = tid >> 4;
        float accA[4] = {0,0,0,0}, accB[4] = {0,0,0,0};
        #pragma unroll 4
        for (int k = 0; k < 128; k++) {
            float a0 = pool[tb * SA1_STRIDE + k];
            float a1 = pool[(tb + 16) * SA1_STRIDE + k];
            #pragma unroll
            for (int i = 0; i < 4; i++) {
                float w = pool[SW1_OFF + (te * 4 + i) * SW1_STRIDE + k];
                accA[i] += a0 * w;
                accB[i] += a1 * w;
            }
        }
        #pragma unroll
        for (int i = 0; i < 4; i++) {
            g_pxp[((size_t)ks * B_ + tb     ) * D_ + e0 + te * 4 + i] = accA[i];
            g_pxp[((size_t)ks * B_ + tb + 16) * D_ + e0 + te * 4 + i] = accB[i];
        }
    } else if (bid < 144) {
        // idle in phase 1 -> preload phase-2 attn weights (keym tile + mkeys) into pool
        int ks = bid & 15;
        int k0 = ks * 64;
        int e = tid >> 2, q = tid & 3;
        const float4* src = (const float4*)(keym + (size_t)e * D_ + k0) + q;
        #pragma unroll
        for (int i = 0; i < 4; i++) {
            float4 t = src[i * 4];
            *(float4*)&pool[SW2_OFF + e * SW2_STRIDE + (q + i * 4) * 4] = t;
        }
        if (tid >= 192) {
            int i = tid - 192;
            pool[MK0_OFF + i] = mkey0[k0 + i];
            pool[MK1_OFF + i] = mkey1[k0 + i];
        }
    }

    gridBarrier();

    // ===== Phase 2: MLP GEMM + attention-logits GEMM (144 tiles) =====
    if (bid < 144) {
        int et = bid >> 4, ks = bid & 15;   // et 0..8, ks 0..15
        int k0 = ks * 64;
        bool attn = (et == 8);
        if (!attn) {   // weight tile 64x64 coalesced (attn blocks preloaded during phase 1)
            int e = tid >> 2, q = tid & 3;
            const float4* src = (const float4*)(W1 + (size_t)(et * 64 + e) * D_ + k0) + q;
            #pragma unroll
            for (int i = 0; i < 4; i++) {
                float4 t = src[i * 4];
                *(float4*)&pool[SW2_OFF + e * SW2_STRIDE + (q + i * 4) * 4] = t;
            }
        }
        {   // A 32x64: reduce 8 xp partials + bias (identical order everywhere)
            int bb  = tid >> 3;
            int kk0 = (tid & 7) * 8;
            float4 acc[2] = {{0,0,0,0},{0,0,0,0}};
            #pragma unroll
            for (int s = 0; s < 8; s++) {
                const float4* src = (const float4*)(g_pxp + ((size_t)s * B_ + bb) * D_ + k0 + kk0);
                #pragma unroll
                for (int j = 0; j < 2; j++) {
                    float4 v = src[j];
                    acc[j].x += v.x; acc[j].y += v.y; acc[j].z += v.z; acc[j].w += v.w;
                }
            }
            const float4* bv = (const float4*)(xa_b + k0 + kk0);
            #pragma unroll
            for (int j = 0; j < 2; j++) {
                float4 bb4 = bv[j];
                pool[bb * SA2_STRIDE + kk0 + 4*j + 0] = acc[j].x + bb4.x;
                pool[bb * SA2_STRIDE + kk0 + 4*j + 1] = acc[j].y + bb4.y;
                pool[bb * SA2_STRIDE + kk0 + 4*j + 2] = acc[j].z + bb4.z;
                pool[bb * SA2_STRIDE + kk0 + 4*j + 3] = acc[j].w + bb4.w;
            }
        }
        __syncthreads();
        int tb = tid & 15, te = tid >> 4;
        float accA[4] = {0,0,0,0}, accB[4] = {0,0,0,0};
        #pragma unroll 4
        for (int k = 0; k < 64; k++) {
            float a0 = pool[tb * SA2_STRIDE + k];
            float a1 = pool[(tb + 16) * SA2_STRIDE + k];
            #pragma unroll
            for (int i = 0; i < 4; i++) {
                float w = pool[SW2_OFF + (te * 4 + i) * SW2_STRIDE + k];
                accA[i] += a0 * w;
                accB[i] += a1 * w;
            }
        }
        if (!attn) {
            int e0 = et * 64;
            #pragma unroll
            for (int i = 0; i < 4; i++) {
                g_ph[((size_t)ks * B_ + tb     ) * HID_ + e0 + te * 4 + i] = accA[i];
                g_ph[((size_t)ks * B_ + tb + 16) * HID_ + e0 + te * 4 + i] = accB[i];
            }
        } else {
            #pragma unroll
            for (int i = 0; i < 4; i++) {
                g_psim[((size_t)ks * B_ + tb     ) * MEM_ + te * 4 + i] = accA[i];
                g_psim[((size_t)ks * B_ + tb + 16) * MEM_ + te * 4 + i] = accB[i];
            }
            if (tid < 64) {
                float s = 0.f;
                #pragma unroll 8
                for (int k = 0; k < 64; k++) { float w = pool[SW2_OFF + tid * SW2_STRIDE + k]; s += w * w; }
                g_pksq[ks * MEM_ + tid] = s;
            } else if (tid < 96) {
                int bb = tid - 64;
                float sx = 0.f, s0 = 0.f, s1 = 0.f;
                #pragma unroll 8
                for (int k = 0; k < 64; k++) {
                    float a = pool[bb * SA2_STRIDE + k];
                    sx += a * a;
                    s0 += a * pool[MK0_OFF + k];
                    s1 += a * pool[MK1_OFF + k];
                }
                g_pxsq[ks * B_ + bb] = sx;
                g_pd0 [ks * B_ + bb] = s0;
                g_pd1 [ks * B_ + bb] = s1;
            } else if (tid == 96) {
                float s = 0.f;
                #pragma unroll 8
                for (int k = 0; k < 64; k++) s += pool[MK0_OFF + k] * pool[MK0_OFF + k];
                g_pn0[ks] = s;
            } else if (tid == 97) {
                float s = 0.f;
                #pragma unroll 8
                for (int k = 0; k < 64; k++) s += pool[MK1_OFF + k] * pool[MK1_OFF + k];
                g_pn1[ks] = s;
            }
        }
    }

    gridBarrier();

    // ===== Phase 3: tail (32 tiles, one per batch) =====
    if (bid < B_) {
        int b = bid;
        int lane = tid & 31;
        int w = tid >> 5;
        float* logits = pool;        // [64]
        float* sc     = pool + 64;   // [8]
        float* rbuf   = pool + 72;   // [8]

        float2 th[16];
        #pragma unroll
        for (int s = 0; s < 16; s++)
            th[s] = ((const float2*)(g_ph + ((size_t)s * B_ + b) * HID_))[tid];

        float simsum = 0.f, ksum = 0.f;
        if (tid < MEM_) {
            #pragma unroll
            for (int s = 0; s < 16; s++) simsum += g_psim[((size_t)s * B_ + b) * MEM_ + tid];
            #pragma unroll
            for (int s = 0; s < 16; s++) ksum += g_pksq[s * MEM_ + tid];
        } else if (tid >= 64 && tid < 72) {
            int j = tid - 64;
            float s = 0.f;
            if (j < 3) {
                const float* src = (j == 0) ? g_pxsq : (j == 1) ? g_pd0 : g_pd1;
                #pragma unroll
                for (int k = 0; k < 16; k++) s += src[k * B_ + b];
            } else if (j < 6) {
                if (b > 0) {
                    const float* src = (j == 3) ? g_pxsq : (j == 4) ? g_pd0 : g_pd1;
                    #pragma unroll
                    for (int k = 0; k < 16; k++) s += src[k * B_ + (b - 1)];
                }
            } else {
                const float* src = (j == 6) ? g_pn0 : g_pn1;
                #pragma unroll
                for (int k = 0; k < 16; k++) s += src[k];
            }
            sc[j] = s;
        }
        __syncthreads();

        float nx = sqrtf(sc[0]);
        if (tid < MEM_) {
            float nk = sqrtf(ksum);
            logits[tid] = simsum / fmaxf(nx, 1e-12f) / fmaxf(nk, 1e-12f) * (1.0f / 32.0f);
        }

        float2 b1v = ((const float2*)mlp_b1)[tid];
        float2 w2v = ((const float2*)w2)[tid];
        float2 hv = {0.f, 0.f};
        #pragma unroll
        for (int s = 0; s < 16; s++) { hv.x += th[s].x; hv.y += th[s].y; }
        hv.x += b1v.x; hv.y += b1v.y;
        float h0 = hv.x / (1.0f + expf(-hv.x));
        float h1 = hv.y / (1.0f + expf(-hv.y));
        float mp = h0 * w2v.x + h1 * w2v.y;
        #pragma unroll
        for (int o = 16; o > 0; o >>= 1) mp += __shfl_down_sync(0xffffffffu, mp, o);
        __syncthreads();                    // orders logits[] before softmax read
        if (lane == 0) rbuf[w] = mp;
        __syncthreads();
        float mlp_out = rbuf[0];
        #pragma unroll
        for (int i = 1; i < 8; i++) mlp_out += rbuf[i];
        mlp_out += b2[0];

        float sn0 = sqrtf(sc[6]), sn1 = sqrtf(sc[7]);
        float s0 = sc[1] / fmaxf(nx * sn0, 1e-8f);
        float s1 = sc[2] / fmaxf(nx * sn1, 1e-8f);
        int best = (s1 > s0) ? 1 : 0;
        float changed = 1.0f;
        if (b > 0) {
            float pn  = sqrtf(sc[3]);
            float ps0 = sc[4] / fmaxf(pn * sn0, 1e-8f);
            float ps1 = sc[5] / fmaxf(pn * sn1, 1e-8f);
            int pbest = (ps1 > ps0) ? 1 : 0;
            changed = (best != pbest) ? 1.0f : 0.0f;
        }

        if (tid < 32) {
            float l0 = logits[tid], l1 = logits[tid + 32];
            float mx = fmaxf(l0, l1);
            #pragma unroll
            for (int o = 16; o > 0; o >>= 1) mx = fmaxf(mx, __shfl_xor_sync(0xffffffffu, mx, o));
            float e0 = expf(l0 - mx), e1 = expf(l1 - mx);
            float ssum = e0 + e1;
            float vsum = e0 * valm[tid] + e1 * valm[tid + 32];
            #pragma unroll
            for (int o = 16; o > 0; o >>= 1) {
                ssum += __shfl_down_sync(0xffffffffu, ssum, o);
                vsum += __shfl_down_sync(0xffffffffu, vsum, o);
            }
            if (tid == 0) {
                float mem_val = vsum / ssum;
                out[b]      = (changed > thr[0]) ? 1.0f : 0.0f;
                out[B_ + b] = cw[0] * mem_val + cw[1] * mlp_out + cb[0];
            }
        }
    }
}

// ---------------- launch ----------------
extern "C" void kernel_launch(void* const* d_in, const int* in_sizes, int n_in,
                              void* d_out, int out_size) {
    const float* x       = (const float*)d_in[0];
    const float* mkey0   = (const float*)d_in[1];
    const float* mkey1   = (const float*)d_in[2];
    const float* keym    = (const float*)d_in[3];
    const float* valm    = (const float*)d_in[4];
    const float* mlp_w1  = (const float*)d_in[5];
    const float* mlp_b1  = (const float*)d_in[6];
    const float* mlp_w2  = (const float*)d_in[7];
    const float* mlp_b2  = (const float*)d_in[8];
    const float* cw      = (const float*)d_in[9];
    const float* cb      = (const float*)d_in[10];
    const float* xa_w    = (const float*)d_in[11];
    const float* xa_b    = (const float*)d_in[12];
    const float* thr     = (const float*)d_in[13];
    float* out = (float*)d_out;

    cudaFuncSetAttribute(k_all, cudaFuncAttributeMaxDynamicSharedMemorySize, SMEM_BYTES);
    k_all<<<NB_, 256, SMEM_BYTES>>>(x, mkey0, mkey1, keym, valm,
                                    mlp_w1, mlp_b1, mlp_w2, mlp_b2,
                                    cw, cb, xa_w, xa_b, thr, out);
}

// round 12
// speedup vs baseline: 1.1648x; 1.0372x over previous
#include <cuda_runtime.h>
#include <math.h>

#define B_   32
#define T_   2048
#define D_   1024
#define MEM_ 64
#define HID_ 512   // D/2
#define NC_  8     // time chunks per batch in mean phase
#define NT0_ (B_ * NC_)   // 256 phase-0 tiles
#define NB_  296   // 2 blocks/SM x 148 SMs; co-residency via __launch_bounds__(256,2)

// ---------------- device scratch (no allocations allowed) ----------------
__device__ __align__(16) float g_part[B_ * NC_ * D_];  // mean partials [b][c][d]
__device__ __align__(16) float g_pxp [8 * B_ * D_];    // xp partials   [ks][b][e]
__device__ __align__(16) float g_ph  [16 * B_ * HID_]; // h partials    [ks][b][j]
__device__ __align__(16) float g_psim[16 * B_ * MEM_]; // sims partials [ks][b][m]
__device__ __align__(16) float g_pksq[16 * MEM_];      // |key|^2 partials
__device__ float g_pxsq[16 * B_];
__device__ float g_pd0 [16 * B_];
__device__ float g_pd1 [16 * B_];
__device__ float g_pn0 [16];
__device__ float g_pn1 [16];
__device__ unsigned long long g_bar;   // monotonic grid-barrier counter (never reset -> replay safe)

// ---------------- dynamic smem pool layout (strides mult-of-4 for LDS.128) ----------------
#define SA1_STRIDE 132
#define SW1_OFF    (32 * SA1_STRIDE)              // 4224 floats
#define SW1_STRIDE 132
#define POOL_FLOATS (SW1_OFF + 64 * SW1_STRIDE)   // 12672 floats
#define SMEM_BYTES  (POOL_FLOATS * 4)             // 50688 B
#define SA2_STRIDE 68
#define SW2_OFF    (32 * SA2_STRIDE)              // 2176
#define SW2_STRIDE 68
#define MK0_OFF    (SW2_OFF + 64 * SW2_STRIDE)    // 6528
#define MK1_OFF    (MK0_OFF + 64)                 // 6592

// ---------------- grid barrier: monotonic counter, all NB_ blocks resident ----------------
__device__ __forceinline__ void gridBarrier() {
    __threadfence();
    __syncthreads();
    if (threadIdx.x == 0) {
        unsigned long long a = atomicAdd(&g_bar, 1ULL);
        unsigned long long target = (a / NB_ + 1ULL) * (unsigned long long)NB_;
        volatile unsigned long long* p = &g_bar;
        while (*p < target) { }
        __threadfence();
    }
    __syncthreads();
}

__global__ __launch_bounds__(256, 2) void k_all(
    const float* __restrict__ x,
    const float* __restrict__ mkey0, const float* __restrict__ mkey1,
    const float* __restrict__ keym,  const float* __restrict__ valm,
    const float* __restrict__ W1,    const float* __restrict__ mlp_b1,
    const float* __restrict__ w2,    const float* __restrict__ b2,
    const float* __restrict__ cw,    const float* __restrict__ cb,
    const float* __restrict__ Wxa,   const float* __restrict__ xa_b,
    const float* __restrict__ thr,   float* __restrict__ out) {
    extern __shared__ __align__(16) float pool[];
    int bid = blockIdx.x;
    int tid = threadIdx.x;

    // ===== P1 weight preload (blocks 0..127): latency hides under phase 0 =====
    if (bid < 128) {
        int et = bid >> 3;
        int e = tid >> 2, q = tid & 3;
        const float4* src = (const float4*)(Wxa + (size_t)(et * 64 + e) * D_ + (bid & 7) * 128) + q;
        #pragma unroll
        for (int i = 0; i < 8; i++) {
            float4 t = src[i * 4];
            *(float4*)&pool[SW1_OFF + e * SW1_STRIDE + (q + i * 4) * 4] = t;
        }
    }

    // ===== Phase 0: mean over T, partial sums (256 tiles: [batch][chunk of 256]) =====
    if (bid < NT0_) {
        int b = bid >> 3;          // 0..31
        int c = bid & 7;           // 0..7
        const float4* p = (const float4*)(x + ((size_t)b * T_ + (size_t)c * 256) * D_) + tid;
        float4 a0 = {0,0,0,0}, a1 = a0, a2 = a0, a3 = a0, a4 = a0, a5 = a0, a6 = a0, a7 = a0;
        for (int t = 0; t < 256; t += 8) {
            float4 v0 = __ldcs(&p[(t + 0) * (D_/4)]);
            float4 v1 = __ldcs(&p[(t + 1) * (D_/4)]);
            float4 v2 = __ldcs(&p[(t + 2) * (D_/4)]);
            float4 v3 = __ldcs(&p[(t + 3) * (D_/4)]);
            float4 v4 = __ldcs(&p[(t + 4) * (D_/4)]);
            float4 v5 = __ldcs(&p[(t + 5) * (D_/4)]);
            float4 v6 = __ldcs(&p[(t + 6) * (D_/4)]);
            float4 v7 = __ldcs(&p[(t + 7) * (D_/4)]);
            a0.x += v0.x; a0.y += v0.y; a0.z += v0.z; a0.w += v0.w;
            a1.x += v1.x; a1.y += v1.y; a1.z += v1.z; a1.w += v1.w;
            a2.x += v2.x; a2.y += v2.y; a2.z += v2.z; a2.w += v2.w;
            a3.x += v3.x; a3.y += v3.y; a3.z += v3.z; a3.w += v3.w;
            a4.x += v4.x; a4.y += v4.y; a4.z += v4.z; a4.w += v4.w;
            a5.x += v5.x; a5.y += v5.y; a5.z += v5.z; a5.w += v5.w;
            a6.x += v6.x; a6.y += v6.y; a6.z += v6.z; a6.w += v6.w;
            a7.x += v7.x; a7.y += v7.y; a7.z += v7.z; a7.w += v7.w;
        }
        float4 s;
        s.x = ((a0.x + a1.x) + (a2.x + a3.x)) + ((a4.x + a5.x) + (a6.x + a7.x));
        s.y = ((a0.y + a1.y) + (a2.y + a3.y)) + ((a4.y + a5.y) + (a6.y + a7.y));
        s.z = ((a0.z + a1.z) + (a2.z + a3.z)) + ((a4.z + a5.z) + (a6.z + a7.z));
        s.w = ((a0.w + a1.w) + (a2.w + a3.w)) + ((a4.w + a5.w) + (a6.w + a7.w));
        ((float4*)g_part)[(b * NC_ + c) * (D_/4) + tid] = s;
    }

    gridBarrier();

    // ===== Phase 1: xp split-K GEMM (128 tiles; weights already in smem) =====
    if (bid < 128) {
        int et = bid >> 3, ks = bid & 7;
        int e0 = et * 64, k0 = ks * 128;
        {   // A 32x128: reduce 8 time-chunk partials * 1/T
            int bb  = tid >> 3;
            int kk0 = (tid & 7) * 16;
            float4 acc[4] = {{0,0,0,0},{0,0,0,0},{0,0,0,0},{0,0,0,0}};
            #pragma unroll
            for (int c = 0; c < NC_; c++) {
                const float4* src = (const float4*)(g_part + ((size_t)bb * NC_ + c) * D_ + k0 + kk0);
                #pragma unroll
                for (int j = 0; j < 4; j++) {
                    float4 v = src[j];
                    acc[j].x += v.x; acc[j].y += v.y; acc[j].z += v.z; acc[j].w += v.w;
                }
            }
            const float invT = 1.0f / (float)T_;
            #pragma unroll
            for (int j = 0; j < 4; j++) {
                float4 o;
                o.x = acc[j].x * invT; o.y = acc[j].y * invT;
                o.z = acc[j].z * invT; o.w = acc[j].w * invT;
                *(float4*)&pool[bb * SA1_STRIDE + kk0 + 4*j] = o;
            }
        }
        __syncthreads();
        int tb = tid & 15, te = tid >> 4;
        float accA[4] = {0,0,0,0}, accB[4] = {0,0,0,0};
        #pragma unroll 8
        for (int k4 = 0; k4 < 32; k4++) {
            float4 a0 = *(const float4*)&pool[tb * SA1_STRIDE + k4 * 4];
            float4 a1 = *(const float4*)&pool[(tb + 16) * SA1_STRIDE + k4 * 4];
            #pragma unroll
            for (int i = 0; i < 4; i++) {
                float4 w = *(const float4*)&pool[SW1_OFF + (te * 4 + i) * SW1_STRIDE + k4 * 4];
                accA[i] += (a0.x*w.x + a0.y*w.y) + (a0.z*w.z + a0.w*w.w);
                accB[i] += (a1.x*w.x + a1.y*w.y) + (a1.z*w.z + a1.w*w.w);
            }
        }
        float4 oa = {accA[0], accA[1], accA[2], accA[3]};
        float4 ob = {accB[0], accB[1], accB[2], accB[3]};
        *(float4*)&g_pxp[((size_t)ks * B_ + tb     ) * D_ + e0 + te * 4] = oa;
        *(float4*)&g_pxp[((size_t)ks * B_ + tb + 16) * D_ + e0 + te * 4] = ob;
    } else if (bid < 144) {
        // idle in phase 1 -> preload phase-2 attn weights (keym tile + mkeys) into pool
        int ks = bid & 15;
        int k0 = ks * 64;
        int e = tid >> 2, q = tid & 3;
        const float4* src = (const float4*)(keym + (size_t)e * D_ + k0) + q;
        #pragma unroll
        for (int i = 0; i < 4; i++) {
            float4 t = src[i * 4];
            *(float4*)&pool[SW2_OFF + e * SW2_STRIDE + (q + i * 4) * 4] = t;
        }
        if (tid >= 192) {
            int i = tid - 192;
            pool[MK0_OFF + i] = mkey0[k0 + i];
            pool[MK1_OFF + i] = mkey1[k0 + i];
        }
    }

    gridBarrier();

    // ===== Phase 2: MLP GEMM + attention-logits GEMM (144 tiles) =====
    if (bid < 144) {
        int et = bid >> 4, ks = bid & 15;   // et 0..8, ks 0..15
        int k0 = ks * 64;
        bool attn = (et == 8);
        if (!attn) {   // weight tile 64x64 coalesced (attn blocks preloaded in phase 1)
            int e = tid >> 2, q = tid & 3;
            const float4* src = (const float4*)(W1 + (size_t)(et * 64 + e) * D_ + k0) + q;
            #pragma unroll
            for (int i = 0; i < 4; i++) {
                float4 t = src[i * 4];
                *(float4*)&pool[SW2_OFF + e * SW2_STRIDE + (q + i * 4) * 4] = t;
            }
        }
        {   // A 32x64: reduce 8 xp partials + bias (identical order everywhere)
            int bb  = tid >> 3;
            int kk0 = (tid & 7) * 8;
            float4 acc[2] = {{0,0,0,0},{0,0,0,0}};
            #pragma unroll
            for (int s = 0; s < 8; s++) {
                const float4* src = (const float4*)(g_pxp + ((size_t)s * B_ + bb) * D_ + k0 + kk0);
                #pragma unroll
                for (int j = 0; j < 2; j++) {
                    float4 v = src[j];
                    acc[j].x += v.x; acc[j].y += v.y; acc[j].z += v.z; acc[j].w += v.w;
                }
            }
            const float4* bv = (const float4*)(xa_b + k0 + kk0);
            #pragma unroll
            for (int j = 0; j < 2; j++) {
                float4 bb4 = bv[j];
                float4 o;
                o.x = acc[j].x + bb4.x; o.y = acc[j].y + bb4.y;
                o.z = acc[j].z + bb4.z; o.w = acc[j].w + bb4.w;
                *(float4*)&pool[bb * SA2_STRIDE + kk0 + 4*j] = o;
            }
        }
        __syncthreads();
        int tb = tid & 15, te = tid >> 4;
        float accA[4] = {0,0,0,0}, accB[4] = {0,0,0,0};
        #pragma unroll 4
        for (int k4 = 0; k4 < 16; k4++) {
            float4 a0 = *(const float4*)&pool[tb * SA2_STRIDE + k4 * 4];
            float4 a1 = *(const float4*)&pool[(tb + 16) * SA2_STRIDE + k4 * 4];
            #pragma unroll
            for (int i = 0; i < 4; i++) {
                float4 w = *(const float4*)&pool[SW2_OFF + (te * 4 + i) * SW2_STRIDE + k4 * 4];
                accA[i] += (a0.x*w.x + a0.y*w.y) + (a0.z*w.z + a0.w*w.w);
                accB[i] += (a1.x*w.x + a1.y*w.y) + (a1.z*w.z + a1.w*w.w);
            }
        }
        float4 oa = {accA[0], accA[1], accA[2], accA[3]};
        float4 ob = {accB[0], accB[1], accB[2], accB[3]};
        if (!attn) {
            int e0 = et * 64;
            *(float4*)&g_ph[((size_t)ks * B_ + tb     ) * HID_ + e0 + te * 4] = oa;
            *(float4*)&g_ph[((size_t)ks * B_ + tb + 16) * HID_ + e0 + te * 4] = ob;
        } else {
            *(float4*)&g_psim[((size_t)ks * B_ + tb     ) * MEM_ + te * 4] = oa;
            *(float4*)&g_psim[((size_t)ks * B_ + tb + 16) * MEM_ + te * 4] = ob;
            if (tid < 64) {
                float s = 0.f;
                #pragma unroll
                for (int k4 = 0; k4 < 16; k4++) {
                    float4 w = *(const float4*)&pool[SW2_OFF + tid * SW2_STRIDE + k4 * 4];
                    s += (w.x*w.x + w.y*w.y) + (w.z*w.z + w.w*w.w);
                }
                g_pksq[ks * MEM_ + tid] = s;
            } else if (tid < 96) {
                int bb = tid - 64;
                float sx = 0.f, s0 = 0.f, s1 = 0.f;
                #pragma unroll
                for (int k4 = 0; k4 < 16; k4++) {
                    float4 a  = *(const float4*)&pool[bb * SA2_STRIDE + k4 * 4];
                    float4 m0 = *(const float4*)&pool[MK0_OFF + k4 * 4];
                    float4 m1 = *(const float4*)&pool[MK1_OFF + k4 * 4];
                    sx += (a.x*a.x + a.y*a.y) + (a.z*a.z + a.w*a.w);
                    s0 += (a.x*m0.x + a.y*m0.y) + (a.z*m0.z + a.w*m0.w);
                    s1 += (a.x*m1.x + a.y*m1.y) + (a.z*m1.z + a.w*m1.w);
                }
                g_pxsq[ks * B_ + bb] = sx;
                g_pd0 [ks * B_ + bb] = s0;
                g_pd1 [ks * B_ + bb] = s1;
            } else if (tid == 96) {
                float s = 0.f;
                #pragma unroll
                for (int k4 = 0; k4 < 16; k4++) {
                    float4 m0 = *(const float4*)&pool[MK0_OFF + k4 * 4];
                    s += (m0.x*m0.x + m0.y*m0.y) + (m0.z*m0.z + m0.w*m0.w);
                }
                g_pn0[ks] = s;
            } else if (tid == 97) {
                float s = 0.f;
                #pragma unroll
                for (int k4 = 0; k4 < 16; k4++) {
                    float4 m1 = *(const float4*)&pool[MK1_OFF + k4 * 4];
                    s += (m1.x*m1.x + m1.y*m1.y) + (m1.z*m1.z + m1.w*m1.w);
                }
                g_pn1[ks] = s;
            }
        }
    }

    gridBarrier();

    // ===== Phase 3: tail (32 tiles, one per batch) =====
    if (bid < B_) {
        int b = bid;
        int lane = tid & 31;
        int w = tid >> 5;
        float* logits = pool;        // [64]
        float* sc     = pool + 64;   // [8]
        float* rbuf   = pool + 72;   // [8]

        float2 th[16];
        #pragma unroll
        for (int s = 0; s < 16; s++)
            th[s] = ((const float2*)(g_ph + ((size_t)s * B_ + b) * HID_))[tid];

        float simsum = 0.f, ksum = 0.f;
        if (tid < MEM_) {
            #pragma unroll
            for (int s = 0; s < 16; s++) simsum += g_psim[((size_t)s * B_ + b) * MEM_ + tid];
            #pragma unroll
            for (int s = 0; s < 16; s++) ksum += g_pksq[s * MEM_ + tid];
        } else if (tid >= 64 && tid < 72) {
            int j = tid - 64;
            float s = 0.f;
            if (j < 3) {
                const float* src = (j == 0) ? g_pxsq : (j == 1) ? g_pd0 : g_pd1;
                #pragma unroll
                for (int k = 0; k < 16; k++) s += src[k * B_ + b];
            } else if (j < 6) {
                if (b > 0) {
                    const float* src = (j == 3) ? g_pxsq : (j == 4) ? g_pd0 : g_pd1;
                    #pragma unroll
                    for (int k = 0; k < 16; k++) s += src[k * B_ + (b - 1)];
                }
            } else {
                const float* src = (j == 6) ? g_pn0 : g_pn1;
                #pragma unroll
                for (int k = 0; k < 16; k++) s += src[k];
            }
            sc[j] = s;
        }
        __syncthreads();

        float nx = sqrtf(sc[0]);
        if (tid < MEM_) {
            float nk = sqrtf(ksum);
            logits[tid] = simsum / fmaxf(nx, 1e-12f) / fmaxf(nk, 1e-12f) * (1.0f / 32.0f);
        }

        float2 b1v = ((const float2*)mlp_b1)[tid];
        float2 w2v = ((const float2*)w2)[tid];
        float2 hv = {0.f, 0.f};
        #pragma unroll
        for (int s = 0; s < 16; s++) { hv.x += th[s].x; hv.y += th[s].y; }
        hv.x += b1v.x; hv.y += b1v.y;
        float h0 = hv.x / (1.0f + expf(-hv.x));
        float h1 = hv.y / (1.0f + expf(-hv.y));
        float mp = h0 * w2v.x + h1 * w2v.y;
        #pragma unroll
        for (int o = 16; o > 0; o >>= 1) mp += __shfl_down_sync(0xffffffffu, mp, o);
        __syncthreads();                    // orders logits[] before softmax read
        if (lane == 0) rbuf[w] = mp;
        __syncthreads();
        float mlp_out = rbuf[0];
        #pragma unroll
        for (int i = 1; i < 8; i++) mlp_out += rbuf[i];
        mlp_out += b2[0];

        float sn0 = sqrtf(sc[6]), sn1 = sqrtf(sc[7]);
        float s0 = sc[1] / fmaxf(nx * sn0, 1e-8f);
        float s1 = sc[2] / fmaxf(nx * sn1, 1e-8f);
        int best = (s1 > s0) ? 1 : 0;
        float changed = 1.0f;
        if (b > 0) {
            float pn  = sqrtf(sc[3]);
            float ps0 = sc[4] / fmaxf(pn * sn0, 1e-8f);
            float ps1 = sc[5] / fmaxf(pn * sn1, 1e-8f);
            int pbest = (ps1 > ps0) ? 1 : 0;
            changed = (best != pbest) ? 1.0f : 0.0f;
        }

        if (tid < 32) {
            float l0 = logits[tid], l1 = logits[tid + 32];
            float mx = fmaxf(l0, l1);
            #pragma unroll
            for (int o = 16; o > 0; o >>= 1) mx = fmaxf(mx, __shfl_xor_sync(0xffffffffu, mx, o));
            float e0 = expf(l0 - mx), e1 = expf(l1 - mx);
            float ssum = e0 + e1;
            float vsum = e0 * valm[tid] + e1 * valm[tid + 32];
            #pragma unroll
            for (int o = 16; o > 0; o >>= 1) {
                ssum += __shfl_down_sync(0xffffffffu, ssum, o);
                vsum += __shfl_down_sync(0xffffffffu, vsum, o);
            }
            if (tid == 0) {
                float mem_val = vsum / ssum;
                out[b]      = (changed > thr[0]) ? 1.0f : 0.0f;
                out[B_ + b] = cw[0] * mem_val + cw[1] * mlp_out + cb[0];
            }
        }
    }
}

// ---------------- launch ----------------
extern "C" void kernel_launch(void* const* d_in, const int* in_sizes, int n_in,
                              void* d_out, int out_size) {
    const float* x       = (const float*)d_in[0];
    const float* mkey0   = (const float*)d_in[1];
    const float* mkey1   = (const float*)d_in[2];
    const float* keym    = (const float*)d_in[3];
    const float* valm    = (const float*)d_in[4];
    const float* mlp_w1  = (const float*)d_in[5];
    const float* mlp_b1  = (const float*)d_in[6];
    const float* mlp_w2  = (const float*)d_in[7];
    const float* mlp_b2  = (const float*)d_in[8];
    const float* cw      = (const float*)d_in[9];
    const float* cb      = (const float*)d_in[10];
    const float* xa_w    = (const float*)d_in[11];
    const float* xa_b    = (const float*)d_in[12];
    const float* thr     = (const float*)d_in[13];
    float* out = (float*)d_out;

    cudaFuncSetAttribute(k_all, cudaFuncAttributeMaxDynamicSharedMemorySize, SMEM_BYTES);
    k_all<<<NB_, 256, SMEM_BYTES>>>(x, mkey0, mkey1, keym, valm,
                                    mlp_w1, mlp_b1, mlp_w2, mlp_b2,
                                    cw, cb, xa_w, xa_b, thr, out);
}